// round 11
// baseline (speedup 1.0000x reference)
#include <cuda_runtime.h>
#include <cuda_bf16.h>
#include <math.h>
#include <stdint.h>

// ---------------------------------------------------------------------------
// Two-hop GAT on GB300 — round 10 (audited r9 TF32 tensor-core GEMM).
// GEMMs on mma.sync.m16n8k8 TF32 with 3-term split (fp32-class accuracy).
// Kept: alpha via folded matvecs; fused both-edge-set launches; v4 RED
// scatter; __expf softmax. Epilogue now uses float2 stores.
// ---------------------------------------------------------------------------

#define N_NODES 50000
#define E_EDGES 150000
#define DIM_MAX 512

__device__ float g_bufA[(size_t)N_NODES * DIM_MAX];
__device__ float g_bufB[(size_t)N_NODES * DIM_MAX];
__device__ float g_bufC[(size_t)N_NODES * DIM_MAX];
__device__ float g_as[N_NODES];
__device__ float g_ad[N_NODES];
__device__ float g_ssum[2 * N_NODES];
__device__ unsigned g_m[2 * N_NODES];
__device__ float g_e[2 * E_EDGES];
__device__ float g_ws[DIM_MAX];
__device__ float g_wd[DIM_MAX];

// ------------------------- tf32 helpers ------------------------------------
__device__ __forceinline__ void tf32_split(float x, uint32_t& hi, uint32_t& lo) {
    uint32_t h;
    asm("cvt.rna.tf32.f32 %0, %1;" : "=r"(h) : "f"(x));
    float hf = __uint_as_float(h);
    float l = x - hf;
    uint32_t lw;
    asm("cvt.rna.tf32.f32 %0, %1;" : "=r"(lw) : "f"(l));
    hi = h; lo = lw;
}

__device__ __forceinline__ void mma_tf32(float* d, const uint32_t* a,
                                         uint32_t b0, uint32_t b1) {
    asm volatile(
        "mma.sync.aligned.m16n8k8.row.col.f32.tf32.tf32.f32 "
        "{%0,%1,%2,%3}, {%4,%5,%6,%7}, {%8,%9}, {%0,%1,%2,%3};"
        : "+f"(d[0]), "+f"(d[1]), "+f"(d[2]), "+f"(d[3])
        : "r"(a[0]), "r"(a[1]), "r"(a[2]), "r"(a[3]), "r"(b0), "r"(b1));
}

// ---------------- TF32 GEMM: C = A[MxK] @ B[KxN] (+bias)(relu) -------------
// BM=BN=128, BK=16, 256 threads = 8 warps in 4(m) x 2(n); each warp 32x64.
// Per warp: 2 m-frags x 8 n-frags of m16n8k8; 3 mma per frag per k8 (split).
// smem pitches padded for conflict-free fragment loads (A:20, B:136).
#define A_PITCH 20
#define B_PITCH 136

template <bool BIAS, bool RELU>
__global__ __launch_bounds__(256, 2)
void tf32_gemm_kernel(const float* __restrict__ A, const float* __restrict__ B,
                      const float* __restrict__ bias, float* __restrict__ C,
                      int M, int N, int K) {
    __shared__ uint32_t Ah[128][A_PITCH];
    __shared__ uint32_t Al[128][A_PITCH];
    __shared__ uint32_t Bh[16][B_PITCH];
    __shared__ uint32_t Bl[16][B_PITCH];

    const int tid = threadIdx.x;
    const int lane = tid & 31;
    const int wid = tid >> 5;
    const int warp_m = wid & 3;   // 0..3 -> 32-row slab
    const int warp_n = wid >> 2;  // 0..1 -> 64-col slab
    const int row0 = blockIdx.y * 128;
    const int col0 = blockIdx.x * 128;

    float d[2][8][4];
#pragma unroll
    for (int mf = 0; mf < 2; mf++)
#pragma unroll
        for (int nf = 0; nf < 8; nf++)
#pragma unroll
            for (int r = 0; r < 4; r++) d[mf][nf][r] = 0.f;

    for (int k0 = 0; k0 < K; k0 += 16) {
        // ---- load + split A tile: 128 rows x 16 cols = 512 float4 ----
#pragma unroll
        for (int i = 0; i < 2; i++) {
            int idx = i * 256 + tid;           // 0..511
            int r = idx >> 2;                  // 0..127
            int c4 = (idx & 3) * 4;            // 0,4,8,12
            float4 v = make_float4(0.f, 0.f, 0.f, 0.f);
            if (row0 + r < M) v = *(const float4*)&A[(size_t)(row0 + r) * K + k0 + c4];
            uint32_t h, l;
            tf32_split(v.x, h, l); Ah[r][c4 + 0] = h; Al[r][c4 + 0] = l;
            tf32_split(v.y, h, l); Ah[r][c4 + 1] = h; Al[r][c4 + 1] = l;
            tf32_split(v.z, h, l); Ah[r][c4 + 2] = h; Al[r][c4 + 2] = l;
            tf32_split(v.w, h, l); Ah[r][c4 + 3] = h; Al[r][c4 + 3] = l;
        }
        // ---- load + split B tile: 16 rows x 128 cols = 512 float4 ----
#pragma unroll
        for (int i = 0; i < 2; i++) {
            int idx = i * 256 + tid;
            int r = idx >> 5;                  // 0..15
            int c4 = (idx & 31) * 4;           // 0..124
            float4 v = *(const float4*)&B[(size_t)(k0 + r) * N + col0 + c4];
            uint32_t h, l;
            tf32_split(v.x, h, l); Bh[r][c4 + 0] = h; Bl[r][c4 + 0] = l;
            tf32_split(v.y, h, l); Bh[r][c4 + 1] = h; Bl[r][c4 + 1] = l;
            tf32_split(v.z, h, l); Bh[r][c4 + 2] = h; Bl[r][c4 + 2] = l;
            tf32_split(v.w, h, l); Bh[r][c4 + 3] = h; Bl[r][c4 + 3] = l;
        }
        __syncthreads();

#pragma unroll
        for (int ks = 0; ks < 2; ks++) {
            const int kb = ks * 8;
            // A fragments (m16n8k8, row-major):
            // a0:(g, t) a1:(g+8, t) a2:(g, t+4) a3:(g+8, t+4); g=lane/4, t=lane%4
            uint32_t ah[2][4], al[2][4];
#pragma unroll
            for (int mf = 0; mf < 2; mf++) {
                int mr = warp_m * 32 + mf * 16 + (lane >> 2);
                int kc = kb + (lane & 3);
                ah[mf][0] = Ah[mr][kc];
                ah[mf][1] = Ah[mr + 8][kc];
                ah[mf][2] = Ah[mr][kc + 4];
                ah[mf][3] = Ah[mr + 8][kc + 4];
                al[mf][0] = Al[mr][kc];
                al[mf][1] = Al[mr + 8][kc];
                al[mf][2] = Al[mr][kc + 4];
                al[mf][3] = Al[mr + 8][kc + 4];
            }
#pragma unroll
            for (int nf = 0; nf < 8; nf++) {
                // B fragments (col layout): b0:(t, g) b1:(t+4, g)
                int nc = warp_n * 64 + nf * 8 + (lane >> 2);
                int kr = kb + (lane & 3);
                uint32_t bh0 = Bh[kr][nc], bh1 = Bh[kr + 4][nc];
                uint32_t bl0 = Bl[kr][nc], bl1 = Bl[kr + 4][nc];
#pragma unroll
                for (int mf = 0; mf < 2; mf++) {
                    mma_tf32(d[mf][nf], ah[mf], bh0, bh1);  // hi*hi
                    mma_tf32(d[mf][nf], al[mf], bh0, bh1);  // lo*hi
                    mma_tf32(d[mf][nf], ah[mf], bl0, bl1);  // hi*lo
                }
            }
        }
        __syncthreads();
    }

    // ---- epilogue: C frag c0:(g, 2t) c1:(g, 2t+1) c2:(g+8, 2t) c3:(g+8, 2t+1)
#pragma unroll
    for (int mf = 0; mf < 2; mf++) {
#pragma unroll
        for (int nf = 0; nf < 8; nf++) {
            int mr = row0 + warp_m * 32 + mf * 16 + (lane >> 2);
            int nc = col0 + warp_n * 64 + nf * 8 + 2 * (lane & 3);
            float v0 = d[mf][nf][0], v1 = d[mf][nf][1];
            float v2 = d[mf][nf][2], v3 = d[mf][nf][3];
            if (BIAS) {
                float b0 = bias[nc], b1 = bias[nc + 1];
                v0 += b0; v1 += b1; v2 += b0; v3 += b1;
            }
            if (RELU) {
                v0 = fmaxf(v0, 0.f); v1 = fmaxf(v1, 0.f);
                v2 = fmaxf(v2, 0.f); v3 = fmaxf(v3, 0.f);
            }
            if (mr < M)
                *(float2*)&C[(size_t)mr * N + nc] = make_float2(v0, v1);
            if (mr + 8 < M)
                *(float2*)&C[(size_t)(mr + 8) * N + nc] = make_float2(v2, v3);
        }
    }
}

// -------- tiny matvec: w[k] = dot(W[k, :], a), W row-major [K x C] ---------
__global__ void matvec_kernel(const float* __restrict__ W, const float* __restrict__ a,
                              float* __restrict__ w, int Krows, int C) {
    int warp = (blockIdx.x * blockDim.x + threadIdx.x) >> 5;
    int lane = threadIdx.x & 31;
    if (warp >= Krows) return;
    const float* r = W + (size_t)warp * C;
    float s = 0.f;
    for (int c = lane; c < C; c += 32) s += r[c] * a[c];
#pragma unroll
    for (int o = 16; o; o >>= 1) s += __shfl_xor_sync(0xFFFFFFFFu, s, o);
    if (lane == 0) w[warp] = s;
}

// ----- dual alpha: as = X@ws, ad = X@wd; one warp per node, X read once ----
__global__ void dual_alpha_kernel(const float* __restrict__ X,
                                  const float* __restrict__ ws, const float* __restrict__ wd,
                                  float* __restrict__ out_s, float* __restrict__ out_d,
                                  int n, int C) {
    int warp = (blockIdx.x * blockDim.x + threadIdx.x) >> 5;
    int lane = threadIdx.x & 31;
    if (warp >= n) return;
    const float* r = X + (size_t)warp * C;
    float ss = 0.f, sd = 0.f;
    for (int c = lane * 4; c < C; c += 128) {
        float4 v = *(const float4*)&r[c];
        float4 s4 = *(const float4*)&ws[c];
        float4 d4 = *(const float4*)&wd[c];
        ss += v.x * s4.x + v.y * s4.y + v.z * s4.z + v.w * s4.w;
        sd += v.x * d4.x + v.y * d4.y + v.z * d4.z + v.w * d4.w;
    }
#pragma unroll
    for (int o = 16; o; o >>= 1) {
        ss += __shfl_xor_sync(0xFFFFFFFFu, ss, o);
        sd += __shfl_xor_sync(0xFFFFFFFFu, sd, o);
    }
    if (lane == 0) { out_s[warp] = ss; out_d[warp] = sd; }
}

// ------------------------ init helpers -------------------------------------
__global__ void init_nodes_kernel(unsigned* __restrict__ m, float* __restrict__ s, int n2) {
    int i = blockIdx.x * blockDim.x + threadIdx.x;
    if (i < n2) { m[i] = 0u; s[i] = 0.f; }
}

__global__ void init_agg_kernel(float* __restrict__ agg, const float* __restrict__ b,
                                float scale, int n, int C) {
    int i = blockIdx.x * blockDim.x + threadIdx.x;
    if (i < n * C) agg[i] = scale * b[i % C];
}

// --------------------- monotone float<->uint for atomicMax -----------------
__device__ __forceinline__ unsigned f2mono(float f) {
    unsigned u = __float_as_uint(f);
    return (u & 0x80000000u) ? ~u : (u | 0x80000000u);
}
__device__ __forceinline__ float mono2f(unsigned u) {
    return (u & 0x80000000u) ? __uint_as_float(u & 0x7FFFFFFFu) : __uint_as_float(~u);
}

// ------------- edge kernels: BOTH edge sets in one launch ------------------
__global__ void edge_max2_kernel(const int* __restrict__ src1, const int* __restrict__ dst1,
                                 const int* __restrict__ src2, const int* __restrict__ dst2,
                                 const float* __restrict__ as, const float* __restrict__ ad,
                                 float* __restrict__ ebuf, unsigned* __restrict__ m,
                                 int E, int n) {
    int i = blockIdx.x * blockDim.x + threadIdx.x;
    if (i >= 2 * E) return;
    int set = i >= E;
    int j = i - set * E;
    int s = set ? src2[j] : src1[j];
    int d = set ? dst2[j] : dst1[j];
    float e = as[s] + ad[d];
    e = (e > 0.f) ? e : 0.2f * e;  // leaky relu, slope 0.2
    ebuf[i] = e;
    atomicMax(&m[set * n + d], f2mono(e));
}

__global__ void edge_expsum2_kernel(const int* __restrict__ dst1, const int* __restrict__ dst2,
                                    float* __restrict__ ebuf, const unsigned* __restrict__ m,
                                    float* __restrict__ ssum, int E, int n) {
    int i = blockIdx.x * blockDim.x + threadIdx.x;
    if (i >= 2 * E) return;
    int set = i >= E;
    int j = i - set * E;
    int d = set ? dst2[j] : dst1[j];
    float ex = __expf(ebuf[i] - mono2f(m[set * n + d]));  // MUFU path; arg <= 0
    ebuf[i] = ex;
    atomicAdd(&ssum[set * n + d], ex);
}

// vector red: agg[d, c..c+3] += v  (16B-aligned, PTX ISA 8.1+ / sm_90+)
__device__ __forceinline__ void red_add_v4(float* p, float4 v) {
    asm volatile("red.global.add.v4.f32 [%0], {%1, %2, %3, %4};"
                 :: "l"(p), "f"(v.x), "f"(v.y), "f"(v.z), "f"(v.w)
                 : "memory");
}

// warp per edge over both sets: agg[dst] += (ex/(s+eps)) * Hs[src]
__global__ void edge_scatter2_kernel(const int* __restrict__ src1, const int* __restrict__ dst1,
                                     const int* __restrict__ src2, const int* __restrict__ dst2,
                                     const float* __restrict__ ex, const float* __restrict__ ssum,
                                     const float* __restrict__ Hs, float* __restrict__ agg,
                                     int E, int n, int C) {
    int warp = (blockIdx.x * blockDim.x + threadIdx.x) >> 5;
    int lane = threadIdx.x & 31;
    if (warp >= 2 * E) return;
    int set = warp >= E;
    int j = warp - set * E;
    int s = set ? src2[j] : src1[j];
    int d = set ? dst2[j] : dst1[j];
    float w = ex[warp] / (ssum[set * n + d] + 1e-16f);
    const float* hr = Hs + (size_t)s * C;
    float* ar = agg + (size_t)d * C;
    for (int c = lane * 4; c < C; c += 128) {
        float4 v = *(const float4*)&hr[c];
        v.x *= w; v.y *= w; v.z *= w; v.w *= w;
        red_add_v4(&ar[c], v);
    }
}

// ---------------------------------------------------------------------------
static inline void run_edge_layer(const int* src1, const int* dst1,
                                  const int* src2, const int* dst2,
                                  float* as, float* ad, unsigned* m, float* ssum,
                                  float* ebuf, const float* Hs, float* agg,
                                  int n, int E, int C) {
    int tb = 256;
    init_nodes_kernel<<<(2 * n + tb - 1) / tb, tb>>>(m, ssum, 2 * n);
    edge_max2_kernel<<<(2 * E + tb - 1) / tb, tb>>>(src1, dst1, src2, dst2, as, ad, ebuf, m, E, n);
    edge_expsum2_kernel<<<(2 * E + tb - 1) / tb, tb>>>(dst1, dst2, ebuf, m, ssum, E, n);
    edge_scatter2_kernel<<<((size_t)2 * E * 32 + tb - 1) / tb, tb>>>(src1, dst1, src2, dst2,
                                                                     ebuf, ssum, Hs, agg, E, n, C);
}

static inline void sgemm(const float* A, const float* B, const float* bias, float* C,
                         int M, int N, int K, bool relu, bool has_bias) {
    dim3 grid(N / 128, (M + 127) / 128);
    if (has_bias && relu)
        tf32_gemm_kernel<true, true><<<grid, 256>>>(A, B, bias, C, M, N, K);
    else if (has_bias)
        tf32_gemm_kernel<true, false><<<grid, 256>>>(A, B, bias, C, M, N, K);
    else
        tf32_gemm_kernel<false, false><<<grid, 256>>>(A, B, nullptr, C, M, N, K);
}

extern "C" void kernel_launch(void* const* d_in, const int* in_sizes, int n_in,
                              void* d_out, int out_size) {
    const int D = 512, H = 512, O = 256;
    const float* x   = (const float*)d_in[0];
    const int*   ei1 = (const int*)d_in[1];
    const int*   ei2 = (const int*)d_in[2];
    const float* W1s = (const float*)d_in[3];
    const float* W1d = (const float*)d_in[4];
    const float* a1s = (const float*)d_in[5];
    const float* a1d = (const float*)d_in[6];
    const float* b1  = (const float*)d_in[7];
    const float* Wl1 = (const float*)d_in[8];
    const float* bl1 = (const float*)d_in[9];
    const float* W2s = (const float*)d_in[10];
    const float* W2d = (const float*)d_in[11];
    const float* a2s = (const float*)d_in[12];
    const float* a2d = (const float*)d_in[13];
    const float* b2  = (const float*)d_in[14];
    const float* Wl2 = (const float*)d_in[15];
    const float* bl2 = (const float*)d_in[16];

    int n = in_sizes[0] / D;       // 50000
    int E = in_sizes[1] / 2;       // 150000

    void *pA, *pB, *pC, *pas, *pad, *pm, *ps, *pe, *pws, *pwd;
    cudaGetSymbolAddress(&pA, g_bufA);
    cudaGetSymbolAddress(&pB, g_bufB);
    cudaGetSymbolAddress(&pC, g_bufC);
    cudaGetSymbolAddress(&pas, g_as);
    cudaGetSymbolAddress(&pad, g_ad);
    cudaGetSymbolAddress(&pm, g_m);
    cudaGetSymbolAddress(&ps, g_ssum);
    cudaGetSymbolAddress(&pe, g_e);
    cudaGetSymbolAddress(&pws, g_ws);
    cudaGetSymbolAddress(&pwd, g_wd);
    float* bufA = (float*)pA;
    float* bufB = (float*)pB;
    float* bufC = (float*)pC;
    float* v_as = (float*)pas;
    float* v_ad = (float*)pad;
    unsigned* v_m = (unsigned*)pm;
    float* v_s = (float*)ps;
    float* ebuf = (float*)pe;
    float* v_ws = (float*)pws;
    float* v_wd = (float*)pwd;

    const int* src1 = ei1;          const int* dst1 = ei1 + E;
    const int* src2 = ei2;          const int* dst2 = ei2 + E;

    int tb = 256;

    // ---- Layer 1 ----
    matvec_kernel<<<(D * 32 + tb - 1) / tb, tb>>>(W1s, a1s, v_ws, D, H);
    matvec_kernel<<<(D * 32 + tb - 1) / tb, tb>>>(W1d, a1d, v_wd, D, H);
    dual_alpha_kernel<<<(n * 32 + tb - 1) / tb, tb>>>(x, v_ws, v_wd, v_as, v_ad, n, D);
    sgemm(x, W1s, nullptr, bufA, n, H, D, false, false);   // h1_src
    init_agg_kernel<<<(n * H + tb - 1) / tb, tb>>>(bufC, b1, 2.0f, n, H);
    run_edge_layer(src1, dst1, src2, dst2, v_as, v_ad, v_m, v_s, ebuf, bufA, bufC, n, E, H);

    // ---- lin1 + relu ----
    sgemm(bufC, Wl1, bl1, bufB, n, H, H, true, true);      // hl -> bufB

    // ---- Layer 2 ----
    matvec_kernel<<<(H * 32 + tb - 1) / tb, tb>>>(W2s, a2s, v_ws, H, O);
    matvec_kernel<<<(H * 32 + tb - 1) / tb, tb>>>(W2d, a2d, v_wd, H, O);
    dual_alpha_kernel<<<(n * 32 + tb - 1) / tb, tb>>>(bufB, v_ws, v_wd, v_as, v_ad, n, H);
    sgemm(bufB, W2s, nullptr, bufA, n, O, H, false, false); // h2_src
    init_agg_kernel<<<(n * O + tb - 1) / tb, tb>>>(bufC, b2, 2.0f, n, O);
    run_edge_layer(src1, dst1, src2, dst2, v_as, v_ad, v_m, v_s, ebuf, bufA, bufC, n, E, O);

    // ---- lin2 ----
    sgemm(bufC, Wl2, bl2, (float*)d_out, n, O, O, false, true);
}

// round 14
// speedup vs baseline: 1.1924x; 1.1924x over previous
#include <cuda_runtime.h>
#include <cuda_bf16.h>
#include <math.h>
#include <stdint.h>

// ---------------------------------------------------------------------------
// Two-hop GAT on GB300 — round 14 (audited r13 resubmit).
// r11 (passed, 2017us): TF32 3-split mma GEMM, L1/LDS-bound (L1=62.4%,
// tensor=46.7%). This kernel: smem holds RAW fp32 (split to tf32 hi/lo in
// registers -> halves LDS traffic) + cp.async double-buffered tiles.
// B_PITCH=136 (banks 8t+g all-distinct); A_PITCH=20 (banks 20g+t distinct).
// Kept: alpha via folded matvecs; fused both-edge-set launches; v4 RED
// scatter; __expf softmax.
// ---------------------------------------------------------------------------

#define N_NODES 50000
#define E_EDGES 150000
#define DIM_MAX 512

__device__ float g_bufA[(size_t)N_NODES * DIM_MAX];
__device__ float g_bufB[(size_t)N_NODES * DIM_MAX];
__device__ float g_bufC[(size_t)N_NODES * DIM_MAX];
__device__ float g_as[N_NODES];
__device__ float g_ad[N_NODES];
__device__ float g_ssum[2 * N_NODES];
__device__ unsigned g_m[2 * N_NODES];
__device__ float g_e[2 * E_EDGES];
__device__ float g_ws[DIM_MAX];
__device__ float g_wd[DIM_MAX];

// ------------------------- tf32 helpers ------------------------------------
__device__ __forceinline__ void tf32_split(float x, uint32_t& hi, uint32_t& lo) {
    uint32_t h;
    asm("cvt.rna.tf32.f32 %0, %1;" : "=r"(h) : "f"(x));
    float hf = __uint_as_float(h);
    float l = x - hf;
    uint32_t lw;
    asm("cvt.rna.tf32.f32 %0, %1;" : "=r"(lw) : "f"(l));
    hi = h; lo = lw;
}

__device__ __forceinline__ void mma_tf32(float* d, const uint32_t* a,
                                         uint32_t b0, uint32_t b1) {
    asm volatile(
        "mma.sync.aligned.m16n8k8.row.col.f32.tf32.tf32.f32 "
        "{%0,%1,%2,%3}, {%4,%5,%6,%7}, {%8,%9}, {%0,%1,%2,%3};"
        : "+f"(d[0]), "+f"(d[1]), "+f"(d[2]), "+f"(d[3])
        : "r"(a[0]), "r"(a[1]), "r"(a[2]), "r"(a[3]), "r"(b0), "r"(b1));
}

// ---------------------------- cp.async helpers -----------------------------
__device__ __forceinline__ void cp_async16(uint32_t saddr, const void* gptr, bool pred) {
    int sz = pred ? 16 : 0;
    asm volatile("cp.async.cg.shared.global [%0], [%1], 16, %2;"
                 :: "r"(saddr), "l"(gptr), "r"(sz));
}
__device__ __forceinline__ void cp_commit() {
    asm volatile("cp.async.commit_group;");
}
__device__ __forceinline__ void cp_wait0() {
    asm volatile("cp.async.wait_group 0;");
}

// ---------------- TF32 GEMM: C = A[MxK] @ B[KxN] (+bias)(relu) -------------
// BM=BN=128, BK=16, 256 threads = 8 warps in 4(m) x 2(n); each warp 32x64.
// smem: raw fp32, double-buffered, cp.async-fed. Split to tf32 hi/lo in regs.
#define A_PITCH 20
#define B_PITCH 136

template <bool BIAS, bool RELU>
__global__ __launch_bounds__(256, 2)
void tf32_gemm_kernel(const float* __restrict__ A, const float* __restrict__ B,
                      const float* __restrict__ bias, float* __restrict__ C,
                      int M, int N, int K) {
    __shared__ float Asm[2][128][A_PITCH];
    __shared__ float Bsm[2][16][B_PITCH];

    const int tid = threadIdx.x;
    const int lane = tid & 31;
    const int wid = tid >> 5;
    const int warp_m = wid & 3;   // 0..3 -> 32-row slab
    const int warp_n = wid >> 2;  // 0..1 -> 64-col slab
    const int row0 = blockIdx.y * 128;
    const int col0 = blockIdx.x * 128;

    // cp.async chunk mapping (16B = 4 floats per chunk, 512 chunks per tile)
    const int ar0 = tid >> 2, ac0 = (tid & 3) * 4;
    const int ar1 = (tid + 256) >> 2, ac1 = ((tid + 256) & 3) * 4;
    const int br0 = tid >> 5, bc0 = (tid & 31) * 4;
    const int br1 = (tid + 256) >> 5, bc1 = ((tid + 256) & 31) * 4;

    uint32_t sA[2], sB[2];
    sA[0] = (uint32_t)__cvta_generic_to_shared(&Asm[0][0][0]);
    sA[1] = (uint32_t)__cvta_generic_to_shared(&Asm[1][0][0]);
    sB[0] = (uint32_t)__cvta_generic_to_shared(&Bsm[0][0][0]);
    sB[1] = (uint32_t)__cvta_generic_to_shared(&Bsm[1][0][0]);

    float d[2][8][4];
#pragma unroll
    for (int mf = 0; mf < 2; mf++)
#pragma unroll
        for (int nf = 0; nf < 8; nf++)
#pragma unroll
            for (int r = 0; r < 4; r++) d[mf][nf][r] = 0.f;

    auto issue_tile = [&](int k0, int buf) {
        cp_async16(sA[buf] + (ar0 * A_PITCH + ac0) * 4,
                   &A[(size_t)(row0 + ar0) * K + k0 + ac0], row0 + ar0 < M);
        cp_async16(sA[buf] + (ar1 * A_PITCH + ac1) * 4,
                   &A[(size_t)(row0 + ar1) * K + k0 + ac1], row0 + ar1 < M);
        cp_async16(sB[buf] + (br0 * B_PITCH + bc0) * 4,
                   &B[(size_t)(k0 + br0) * N + col0 + bc0], true);
        cp_async16(sB[buf] + (br1 * B_PITCH + bc1) * 4,
                   &B[(size_t)(k0 + br1) * N + col0 + bc1], true);
        cp_commit();
    };

    issue_tile(0, 0);

    const int ntiles = K >> 4;
    int buf = 0;
    for (int t = 0; t < ntiles; t++) {
        cp_wait0();
        __syncthreads();
        if (t + 1 < ntiles) issue_tile((t + 1) << 4, buf ^ 1);

#pragma unroll
        for (int ks = 0; ks < 2; ks++) {
            const int kb = ks * 8;
            // A fragments: load f32, split in regs.
            // a0:(g,t) a1:(g+8,t) a2:(g,t+4) a3:(g+8,t+4); g=lane/4, t=lane%4
            uint32_t ah[2][4], al[2][4];
#pragma unroll
            for (int mf = 0; mf < 2; mf++) {
                int mr = warp_m * 32 + mf * 16 + (lane >> 2);
                int kc = kb + (lane & 3);
                float f0 = Asm[buf][mr][kc];
                float f1 = Asm[buf][mr + 8][kc];
                float f2 = Asm[buf][mr][kc + 4];
                float f3 = Asm[buf][mr + 8][kc + 4];
                tf32_split(f0, ah[mf][0], al[mf][0]);
                tf32_split(f1, ah[mf][1], al[mf][1]);
                tf32_split(f2, ah[mf][2], al[mf][2]);
                tf32_split(f3, ah[mf][3], al[mf][3]);
            }
#pragma unroll
            for (int nf = 0; nf < 8; nf++) {
                // B fragments (col layout): b0:(t,g) b1:(t+4,g)
                int nc = warp_n * 64 + nf * 8 + (lane >> 2);
                int kr = kb + (lane & 3);
                float bf0 = Bsm[buf][kr][nc];
                float bf1 = Bsm[buf][kr + 4][nc];
                uint32_t bh0, bl0, bh1, bl1;
                tf32_split(bf0, bh0, bl0);
                tf32_split(bf1, bh1, bl1);
#pragma unroll
                for (int mf = 0; mf < 2; mf++) {
                    mma_tf32(d[mf][nf], ah[mf], bh0, bh1);  // hi*hi
                    mma_tf32(d[mf][nf], al[mf], bh0, bh1);  // lo*hi
                    mma_tf32(d[mf][nf], ah[mf], bl0, bl1);  // hi*lo
                }
            }
        }
        __syncthreads();
        buf ^= 1;
    }

    // ---- epilogue: C frag c0:(g,2t) c1:(g,2t+1) c2:(g+8,2t) c3:(g+8,2t+1)
#pragma unroll
    for (int mf = 0; mf < 2; mf++) {
#pragma unroll
        for (int nf = 0; nf < 8; nf++) {
            int mr = row0 + warp_m * 32 + mf * 16 + (lane >> 2);
            int nc = col0 + warp_n * 64 + nf * 8 + 2 * (lane & 3);
            float v0 = d[mf][nf][0], v1 = d[mf][nf][1];
            float v2 = d[mf][nf][2], v3 = d[mf][nf][3];
            if (BIAS) {
                float b0 = bias[nc], b1 = bias[nc + 1];
                v0 += b0; v1 += b1; v2 += b0; v3 += b1;
            }
            if (RELU) {
                v0 = fmaxf(v0, 0.f); v1 = fmaxf(v1, 0.f);
                v2 = fmaxf(v2, 0.f); v3 = fmaxf(v3, 0.f);
            }
            if (mr < M)
                *(float2*)&C[(size_t)mr * N + nc] = make_float2(v0, v1);
            if (mr + 8 < M)
                *(float2*)&C[(size_t)(mr + 8) * N + nc] = make_float2(v2, v3);
        }
    }
}

// -------- tiny matvec: w[k] = dot(W[k, :], a), W row-major [K x C] ---------
__global__ void matvec_kernel(const float* __restrict__ W, const float* __restrict__ a,
                              float* __restrict__ w, int Krows, int C) {
    int warp = (blockIdx.x * blockDim.x + threadIdx.x) >> 5;
    int lane = threadIdx.x & 31;
    if (warp >= Krows) return;
    const float* r = W + (size_t)warp * C;
    float s = 0.f;
    for (int c = lane; c < C; c += 32) s += r[c] * a[c];
#pragma unroll
    for (int o = 16; o; o >>= 1) s += __shfl_xor_sync(0xFFFFFFFFu, s, o);
    if (lane == 0) w[warp] = s;
}

// ----- dual alpha: as = X@ws, ad = X@wd; one warp per node, X read once ----
__global__ void dual_alpha_kernel(const float* __restrict__ X,
                                  const float* __restrict__ ws, const float* __restrict__ wd,
                                  float* __restrict__ out_s, float* __restrict__ out_d,
                                  int n, int C) {
    int warp = (blockIdx.x * blockDim.x + threadIdx.x) >> 5;
    int lane = threadIdx.x & 31;
    if (warp >= n) return;
    const float* r = X + (size_t)warp * C;
    float ss = 0.f, sd = 0.f;
    for (int c = lane * 4; c < C; c += 128) {
        float4 v = *(const float4*)&r[c];
        float4 s4 = *(const float4*)&ws[c];
        float4 d4 = *(const float4*)&wd[c];
        ss += v.x * s4.x + v.y * s4.y + v.z * s4.z + v.w * s4.w;
        sd += v.x * d4.x + v.y * d4.y + v.z * d4.z + v.w * d4.w;
    }
#pragma unroll
    for (int o = 16; o; o >>= 1) {
        ss += __shfl_xor_sync(0xFFFFFFFFu, ss, o);
        sd += __shfl_xor_sync(0xFFFFFFFFu, sd, o);
    }
    if (lane == 0) { out_s[warp] = ss; out_d[warp] = sd; }
}

// ------------------------ init helpers -------------------------------------
__global__ void init_nodes_kernel(unsigned* __restrict__ m, float* __restrict__ s, int n2) {
    int i = blockIdx.x * blockDim.x + threadIdx.x;
    if (i < n2) { m[i] = 0u; s[i] = 0.f; }
}

__global__ void init_agg_kernel(float* __restrict__ agg, const float* __restrict__ b,
                                float scale, int n, int C) {
    int i = blockIdx.x * blockDim.x + threadIdx.x;
    if (i < n * C) agg[i] = scale * b[i % C];
}

// --------------------- monotone float<->uint for atomicMax -----------------
__device__ __forceinline__ unsigned f2mono(float f) {
    unsigned u = __float_as_uint(f);
    return (u & 0x80000000u) ? ~u : (u | 0x80000000u);
}
__device__ __forceinline__ float mono2f(unsigned u) {
    return (u & 0x80000000u) ? __uint_as_float(u & 0x7FFFFFFFu) : __uint_as_float(~u);
}

// ------------- edge kernels: BOTH edge sets in one launch ------------------
__global__ void edge_max2_kernel(const int* __restrict__ src1, const int* __restrict__ dst1,
                                 const int* __restrict__ src2, const int* __restrict__ dst2,
                                 const float* __restrict__ as, const float* __restrict__ ad,
                                 float* __restrict__ ebuf, unsigned* __restrict__ m,
                                 int E, int n) {
    int i = blockIdx.x * blockDim.x + threadIdx.x;
    if (i >= 2 * E) return;
    int set = i >= E;
    int j = i - set * E;
    int s = set ? src2[j] : src1[j];
    int d = set ? dst2[j] : dst1[j];
    float e = as[s] + ad[d];
    e = (e > 0.f) ? e : 0.2f * e;  // leaky relu, slope 0.2
    ebuf[i] = e;
    atomicMax(&m[set * n + d], f2mono(e));
}

__global__ void edge_expsum2_kernel(const int* __restrict__ dst1, const int* __restrict__ dst2,
                                    float* __restrict__ ebuf, const unsigned* __restrict__ m,
                                    float* __restrict__ ssum, int E, int n) {
    int i = blockIdx.x * blockDim.x + threadIdx.x;
    if (i >= 2 * E) return;
    int set = i >= E;
    int j = i - set * E;
    int d = set ? dst2[j] : dst1[j];
    float ex = __expf(ebuf[i] - mono2f(m[set * n + d]));  // MUFU path; arg <= 0
    ebuf[i] = ex;
    atomicAdd(&ssum[set * n + d], ex);
}

// vector red: agg[d, c..c+3] += v  (16B-aligned, PTX ISA 8.1+ / sm_90+)
__device__ __forceinline__ void red_add_v4(float* p, float4 v) {
    asm volatile("red.global.add.v4.f32 [%0], {%1, %2, %3, %4};"
                 :: "l"(p), "f"(v.x), "f"(v.y), "f"(v.z), "f"(v.w)
                 : "memory");
}

// warp per edge over both sets: agg[dst] += (ex/(s+eps)) * Hs[src]
__global__ void edge_scatter2_kernel(const int* __restrict__ src1, const int* __restrict__ dst1,
                                     const int* __restrict__ src2, const int* __restrict__ dst2,
                                     const float* __restrict__ ex, const float* __restrict__ ssum,
                                     const float* __restrict__ Hs, float* __restrict__ agg,
                                     int E, int n, int C) {
    int warp = (blockIdx.x * blockDim.x + threadIdx.x) >> 5;
    int lane = threadIdx.x & 31;
    if (warp >= 2 * E) return;
    int set = warp >= E;
    int j = warp - set * E;
    int s = set ? src2[j] : src1[j];
    int d = set ? dst2[j] : dst1[j];
    float w = ex[warp] / (ssum[set * n + d] + 1e-16f);
    const float* hr = Hs + (size_t)s * C;
    float* ar = agg + (size_t)d * C;
    for (int c = lane * 4; c < C; c += 128) {
        float4 v = *(const float4*)&hr[c];
        v.x *= w; v.y *= w; v.z *= w; v.w *= w;
        red_add_v4(&ar[c], v);
    }
}

// ---------------------------------------------------------------------------
static inline void run_edge_layer(const int* src1, const int* dst1,
                                  const int* src2, const int* dst2,
                                  float* as, float* ad, unsigned* m, float* ssum,
                                  float* ebuf, const float* Hs, float* agg,
                                  int n, int E, int C) {
    int tb = 256;
    init_nodes_kernel<<<(2 * n + tb - 1) / tb, tb>>>(m, ssum, 2 * n);
    edge_max2_kernel<<<(2 * E + tb - 1) / tb, tb>>>(src1, dst1, src2, dst2, as, ad, ebuf, m, E, n);
    edge_expsum2_kernel<<<(2 * E + tb - 1) / tb, tb>>>(dst1, dst2, ebuf, m, ssum, E, n);
    edge_scatter2_kernel<<<((size_t)2 * E * 32 + tb - 1) / tb, tb>>>(src1, dst1, src2, dst2,
                                                                     ebuf, ssum, Hs, agg, E, n, C);
}

static inline void sgemm(const float* A, const float* B, const float* bias, float* C,
                         int M, int N, int K, bool relu, bool has_bias) {
    dim3 grid(N / 128, (M + 127) / 128);
    if (has_bias && relu)
        tf32_gemm_kernel<true, true><<<grid, 256>>>(A, B, bias, C, M, N, K);
    else if (has_bias)
        tf32_gemm_kernel<true, false><<<grid, 256>>>(A, B, bias, C, M, N, K);
    else
        tf32_gemm_kernel<false, false><<<grid, 256>>>(A, B, nullptr, C, M, N, K);
}

extern "C" void kernel_launch(void* const* d_in, const int* in_sizes, int n_in,
                              void* d_out, int out_size) {
    const int D = 512, H = 512, O = 256;
    const float* x   = (const float*)d_in[0];
    const int*   ei1 = (const int*)d_in[1];
    const int*   ei2 = (const int*)d_in[2];
    const float* W1s = (const float*)d_in[3];
    const float* W1d = (const float*)d_in[4];
    const float* a1s = (const float*)d_in[5];
    const float* a1d = (const float*)d_in[6];
    const float* b1  = (const float*)d_in[7];
    const float* Wl1 = (const float*)d_in[8];
    const float* bl1 = (const float*)d_in[9];
    const float* W2s = (const float*)d_in[10];
    const float* W2d = (const float*)d_in[11];
    const float* a2s = (const float*)d_in[12];
    const float* a2d = (const float*)d_in[13];
    const float* b2  = (const float*)d_in[14];
    const float* Wl2 = (const float*)d_in[15];
    const float* bl2 = (const float*)d_in[16];

    int n = in_sizes[0] / D;       // 50000
    int E = in_sizes[1] / 2;       // 150000

    void *pA, *pB, *pC, *pas, *pad, *pm, *ps, *pe, *pws, *pwd;
    cudaGetSymbolAddress(&pA, g_bufA);
    cudaGetSymbolAddress(&pB, g_bufB);
    cudaGetSymbolAddress(&pC, g_bufC);
    cudaGetSymbolAddress(&pas, g_as);
    cudaGetSymbolAddress(&pad, g_ad);
    cudaGetSymbolAddress(&pm, g_m);
    cudaGetSymbolAddress(&ps, g_ssum);
    cudaGetSymbolAddress(&pe, g_e);
    cudaGetSymbolAddress(&pws, g_ws);
    cudaGetSymbolAddress(&pwd, g_wd);
    float* bufA = (float*)pA;
    float* bufB = (float*)pB;
    float* bufC = (float*)pC;
    float* v_as = (float*)pas;
    float* v_ad = (float*)pad;
    unsigned* v_m = (unsigned*)pm;
    float* v_s = (float*)ps;
    float* ebuf = (float*)pe;
    float* v_ws = (float*)pws;
    float* v_wd = (float*)pwd;

    const int* src1 = ei1;          const int* dst1 = ei1 + E;
    const int* src2 = ei2;          const int* dst2 = ei2 + E;

    int tb = 256;

    // ---- Layer 1 ----
    matvec_kernel<<<(D * 32 + tb - 1) / tb, tb>>>(W1s, a1s, v_ws, D, H);
    matvec_kernel<<<(D * 32 + tb - 1) / tb, tb>>>(W1d, a1d, v_wd, D, H);
    dual_alpha_kernel<<<(n * 32 + tb - 1) / tb, tb>>>(x, v_ws, v_wd, v_as, v_ad, n, D);
    sgemm(x, W1s, nullptr, bufA, n, H, D, false, false);   // h1_src
    init_agg_kernel<<<(n * H + tb - 1) / tb, tb>>>(bufC, b1, 2.0f, n, H);
    run_edge_layer(src1, dst1, src2, dst2, v_as, v_ad, v_m, v_s, ebuf, bufA, bufC, n, E, H);

    // ---- lin1 + relu ----
    sgemm(bufC, Wl1, bl1, bufB, n, H, H, true, true);      // hl -> bufB

    // ---- Layer 2 ----
    matvec_kernel<<<(H * 32 + tb - 1) / tb, tb>>>(W2s, a2s, v_ws, H, O);
    matvec_kernel<<<(H * 32 + tb - 1) / tb, tb>>>(W2d, a2d, v_wd, H, O);
    dual_alpha_kernel<<<(n * 32 + tb - 1) / tb, tb>>>(bufB, v_ws, v_wd, v_as, v_ad, n, H);
    sgemm(bufB, W2s, nullptr, bufA, n, O, H, false, false); // h2_src
    init_agg_kernel<<<(n * O + tb - 1) / tb, tb>>>(bufC, b2, 2.0f, n, O);
    run_edge_layer(src1, dst1, src2, dst2, v_as, v_ad, v_m, v_s, ebuf, bufA, bufC, n, E, O);

    // ---- lin2 ----
    sgemm(bufC, Wl2, bl2, (float*)d_out, n, O, O, false, true);
}

// round 15
// speedup vs baseline: 1.2751x; 1.0693x over previous
#include <cuda_runtime.h>
#include <cuda_bf16.h>
#include <math.h>
#include <stdint.h>

// ---------------------------------------------------------------------------
// Two-hop GAT on GB300 — round 15.
// r14 (passed, 1692us): GEMM alu-bound (alu=31%, fma=12.6%, tensor=57.1%)
// from in-register tf32 splits. This round: B hi/lo precomputed ONCE per
// tile into smem (reg-prefetch LDG -> split -> STS overlapped with mma);
// A stays cp.async + in-reg split. BK=8 so double-buffered Bh/Bl fit 48KB.
// Mainloop ALU per 48 mma: 72 -> 24 ops.
// Kept: alpha via folded matvecs; fused both-edge-set launches; v4 RED
// scatter; __expf softmax.
// ---------------------------------------------------------------------------

#define N_NODES 50000
#define E_EDGES 150000
#define DIM_MAX 512

__device__ float g_bufA[(size_t)N_NODES * DIM_MAX];
__device__ float g_bufB[(size_t)N_NODES * DIM_MAX];
__device__ float g_bufC[(size_t)N_NODES * DIM_MAX];
__device__ float g_as[N_NODES];
__device__ float g_ad[N_NODES];
__device__ float g_ssum[2 * N_NODES];
__device__ unsigned g_m[2 * N_NODES];
__device__ float g_e[2 * E_EDGES];
__device__ float g_ws[DIM_MAX];
__device__ float g_wd[DIM_MAX];

// ------------------------- tf32 helpers ------------------------------------
__device__ __forceinline__ void tf32_split(float x, uint32_t& hi, uint32_t& lo) {
    uint32_t h;
    asm("cvt.rna.tf32.f32 %0, %1;" : "=r"(h) : "f"(x));
    float hf = __uint_as_float(h);
    float l = x - hf;
    uint32_t lw;
    asm("cvt.rna.tf32.f32 %0, %1;" : "=r"(lw) : "f"(l));
    hi = h; lo = lw;
}

__device__ __forceinline__ void mma_tf32(float* d, const uint32_t* a,
                                         uint32_t b0, uint32_t b1) {
    asm volatile(
        "mma.sync.aligned.m16n8k8.row.col.f32.tf32.tf32.f32 "
        "{%0,%1,%2,%3}, {%4,%5,%6,%7}, {%8,%9}, {%0,%1,%2,%3};"
        : "+f"(d[0]), "+f"(d[1]), "+f"(d[2]), "+f"(d[3])
        : "r"(a[0]), "r"(a[1]), "r"(a[2]), "r"(a[3]), "r"(b0), "r"(b1));
}

// ---------------------------- cp.async helpers -----------------------------
__device__ __forceinline__ void cp_async16(uint32_t saddr, const void* gptr, bool pred) {
    int sz = pred ? 16 : 0;
    asm volatile("cp.async.cg.shared.global [%0], [%1], 16, %2;"
                 :: "r"(saddr), "l"(gptr), "r"(sz));
}
__device__ __forceinline__ void cp_commit() {
    asm volatile("cp.async.commit_group;");
}
__device__ __forceinline__ void cp_wait0() {
    asm volatile("cp.async.wait_group 0;");
}

// ---------------- TF32 GEMM: C = A[MxK] @ B[KxN] (+bias)(relu) -------------
// BM=BN=128, BK=8, 256 threads = 8 warps in 4(m) x 2(n); each warp 32x64.
// A: cp.async raw fp32, split to hi/lo in regs (pitch 12: banks 12g+t distinct).
// B: LDG reg-prefetch -> split -> STS into double-buffered Bh/Bl smem
//    (pitch 136: banks 8t+g distinct). Smem total 29.7KB.
#define A_PITCH 12
#define B_PITCH 136

template <bool BIAS, bool RELU>
__global__ __launch_bounds__(256, 2)
void tf32_gemm_kernel(const float* __restrict__ A, const float* __restrict__ B,
                      const float* __restrict__ bias, float* __restrict__ C,
                      int M, int N, int K) {
    __shared__ float Asm[2][128][A_PITCH];
    __shared__ uint32_t Bh[2][8][B_PITCH];
    __shared__ uint32_t Bl[2][8][B_PITCH];

    const int tid = threadIdx.x;
    const int lane = tid & 31;
    const int wid = tid >> 5;
    const int warp_m = wid & 3;   // 0..3 -> 32-row slab
    const int warp_n = wid >> 2;  // 0..1 -> 64-col slab
    const int row0 = blockIdx.y * 128;
    const int col0 = blockIdx.x * 128;

    // A cp.async: 128x8 floats = 256 16B-chunks, 1 per thread
    const int ar = tid >> 1, ac = (tid & 1) * 4;
    // B LDG/STS: 8x128 floats = 256 float4, 1 per thread
    const int br = tid >> 5, bc = (tid & 31) * 4;

    uint32_t sA[2];
    sA[0] = (uint32_t)__cvta_generic_to_shared(&Asm[0][0][0]);
    sA[1] = (uint32_t)__cvta_generic_to_shared(&Asm[1][0][0]);

    float d[2][8][4];
#pragma unroll
    for (int mf = 0; mf < 2; mf++)
#pragma unroll
        for (int nf = 0; nf < 8; nf++)
#pragma unroll
            for (int r = 0; r < 4; r++) d[mf][nf][r] = 0.f;

    const bool a_ok = (row0 + ar < M);

    // ---- prologue: tile 0 ----
    {
        cp_async16(sA[0] + (ar * A_PITCH + ac) * 4,
                   &A[(size_t)(row0 + ar) * K + ac], a_ok);
        cp_commit();
        float4 bv = *(const float4*)&B[(size_t)br * N + col0 + bc];
        uint32_t h0, l0, h1, l1, h2, l2, h3, l3;
        tf32_split(bv.x, h0, l0); tf32_split(bv.y, h1, l1);
        tf32_split(bv.z, h2, l2); tf32_split(bv.w, h3, l3);
        *(uint4*)&Bh[0][br][bc] = make_uint4(h0, h1, h2, h3);
        *(uint4*)&Bl[0][br][bc] = make_uint4(l0, l1, l2, l3);
    }

    const int ntiles = K >> 3;
    int buf = 0;
    for (int t = 0; t < ntiles; t++) {
        cp_wait0();
        __syncthreads();

        const bool pre = (t + 1 < ntiles);
        float4 bv;
        if (pre) {
            int kn = (t + 1) << 3;
            cp_async16(sA[buf ^ 1] + (ar * A_PITCH + ac) * 4,
                       &A[(size_t)(row0 + ar) * K + kn + ac], a_ok);
            cp_commit();
            bv = *(const float4*)&B[(size_t)(kn + br) * N + col0 + bc];
        }

        // ---- mma over current buffer (one k8 step) ----
        // A fragments: a0:(g,t) a1:(g+8,t) a2:(g,t+4) a3:(g+8,t+4)
        uint32_t ah[2][4], al[2][4];
#pragma unroll
        for (int mf = 0; mf < 2; mf++) {
            int mr = warp_m * 32 + mf * 16 + (lane >> 2);
            int kc = lane & 3;
            float f0 = Asm[buf][mr][kc];
            float f1 = Asm[buf][mr + 8][kc];
            float f2 = Asm[buf][mr][kc + 4];
            float f3 = Asm[buf][mr + 8][kc + 4];
            tf32_split(f0, ah[mf][0], al[mf][0]);
            tf32_split(f1, ah[mf][1], al[mf][1]);
            tf32_split(f2, ah[mf][2], al[mf][2]);
            tf32_split(f3, ah[mf][3], al[mf][3]);
        }
#pragma unroll
        for (int nf = 0; nf < 8; nf++) {
            // B fragments (col layout): b0:(t,g) b1:(t+4,g)
            int nc = warp_n * 64 + nf * 8 + (lane >> 2);
            int kr = lane & 3;
            uint32_t bh0 = Bh[buf][kr][nc], bh1 = Bh[buf][kr + 4][nc];
            uint32_t bl0 = Bl[buf][kr][nc], bl1 = Bl[buf][kr + 4][nc];
#pragma unroll
            for (int mf = 0; mf < 2; mf++) {
                mma_tf32(d[mf][nf], ah[mf], bh0, bh1);  // hi*hi
                mma_tf32(d[mf][nf], al[mf], bh0, bh1);  // lo*hi
                mma_tf32(d[mf][nf], ah[mf], bl0, bl1);  // hi*lo
            }
        }

        if (pre) {
            uint32_t h0, l0, h1, l1, h2, l2, h3, l3;
            tf32_split(bv.x, h0, l0); tf32_split(bv.y, h1, l1);
            tf32_split(bv.z, h2, l2); tf32_split(bv.w, h3, l3);
            *(uint4*)&Bh[buf ^ 1][br][bc] = make_uint4(h0, h1, h2, h3);
            *(uint4*)&Bl[buf ^ 1][br][bc] = make_uint4(l0, l1, l2, l3);
        }
        buf ^= 1;
    }

    // ---- epilogue: C frag c0:(g,2t) c1:(g,2t+1) c2:(g+8,2t) c3:(g+8,2t+1)
#pragma unroll
    for (int mf = 0; mf < 2; mf++) {
#pragma unroll
        for (int nf = 0; nf < 8; nf++) {
            int mr = row0 + warp_m * 32 + mf * 16 + (lane >> 2);
            int nc = col0 + warp_n * 64 + nf * 8 + 2 * (lane & 3);
            float v0 = d[mf][nf][0], v1 = d[mf][nf][1];
            float v2 = d[mf][nf][2], v3 = d[mf][nf][3];
            if (BIAS) {
                float b0 = bias[nc], b1 = bias[nc + 1];
                v0 += b0; v1 += b1; v2 += b0; v3 += b1;
            }
            if (RELU) {
                v0 = fmaxf(v0, 0.f); v1 = fmaxf(v1, 0.f);
                v2 = fmaxf(v2, 0.f); v3 = fmaxf(v3, 0.f);
            }
            if (mr < M)
                *(float2*)&C[(size_t)mr * N + nc] = make_float2(v0, v1);
            if (mr + 8 < M)
                *(float2*)&C[(size_t)(mr + 8) * N + nc] = make_float2(v2, v3);
        }
    }
}

// -------- tiny matvec: w[k] = dot(W[k, :], a), W row-major [K x C] ---------
__global__ void matvec_kernel(const float* __restrict__ W, const float* __restrict__ a,
                              float* __restrict__ w, int Krows, int C) {
    int warp = (blockIdx.x * blockDim.x + threadIdx.x) >> 5;
    int lane = threadIdx.x & 31;
    if (warp >= Krows) return;
    const float* r = W + (size_t)warp * C;
    float s = 0.f;
    for (int c = lane; c < C; c += 32) s += r[c] * a[c];
#pragma unroll
    for (int o = 16; o; o >>= 1) s += __shfl_xor_sync(0xFFFFFFFFu, s, o);
    if (lane == 0) w[warp] = s;
}

// ----- dual alpha: as = X@ws, ad = X@wd; one warp per node, X read once ----
__global__ void dual_alpha_kernel(const float* __restrict__ X,
                                  const float* __restrict__ ws, const float* __restrict__ wd,
                                  float* __restrict__ out_s, float* __restrict__ out_d,
                                  int n, int C) {
    int warp = (blockIdx.x * blockDim.x + threadIdx.x) >> 5;
    int lane = threadIdx.x & 31;
    if (warp >= n) return;
    const float* r = X + (size_t)warp * C;
    float ss = 0.f, sd = 0.f;
    for (int c = lane * 4; c < C; c += 128) {
        float4 v = *(const float4*)&r[c];
        float4 s4 = *(const float4*)&ws[c];
        float4 d4 = *(const float4*)&wd[c];
        ss += v.x * s4.x + v.y * s4.y + v.z * s4.z + v.w * s4.w;
        sd += v.x * d4.x + v.y * d4.y + v.z * d4.z + v.w * d4.w;
    }
#pragma unroll
    for (int o = 16; o; o >>= 1) {
        ss += __shfl_xor_sync(0xFFFFFFFFu, ss, o);
        sd += __shfl_xor_sync(0xFFFFFFFFu, sd, o);
    }
    if (lane == 0) { out_s[warp] = ss; out_d[warp] = sd; }
}

// ------------------------ init helpers -------------------------------------
__global__ void init_nodes_kernel(unsigned* __restrict__ m, float* __restrict__ s, int n2) {
    int i = blockIdx.x * blockDim.x + threadIdx.x;
    if (i < n2) { m[i] = 0u; s[i] = 0.f; }
}

__global__ void init_agg_kernel(float* __restrict__ agg, const float* __restrict__ b,
                                float scale, int n, int C) {
    int i = blockIdx.x * blockDim.x + threadIdx.x;
    if (i < n * C) agg[i] = scale * b[i % C];
}

// --------------------- monotone float<->uint for atomicMax -----------------
__device__ __forceinline__ unsigned f2mono(float f) {
    unsigned u = __float_as_uint(f);
    return (u & 0x80000000u) ? ~u : (u | 0x80000000u);
}
__device__ __forceinline__ float mono2f(unsigned u) {
    return (u & 0x80000000u) ? __uint_as_float(u & 0x7FFFFFFFu) : __uint_as_float(~u);
}

// ------------- edge kernels: BOTH edge sets in one launch ------------------
__global__ void edge_max2_kernel(const int* __restrict__ src1, const int* __restrict__ dst1,
                                 const int* __restrict__ src2, const int* __restrict__ dst2,
                                 const float* __restrict__ as, const float* __restrict__ ad,
                                 float* __restrict__ ebuf, unsigned* __restrict__ m,
                                 int E, int n) {
    int i = blockIdx.x * blockDim.x + threadIdx.x;
    if (i >= 2 * E) return;
    int set = i >= E;
    int j = i - set * E;
    int s = set ? src2[j] : src1[j];
    int d = set ? dst2[j] : dst1[j];
    float e = as[s] + ad[d];
    e = (e > 0.f) ? e : 0.2f * e;  // leaky relu, slope 0.2
    ebuf[i] = e;
    atomicMax(&m[set * n + d], f2mono(e));
}

__global__ void edge_expsum2_kernel(const int* __restrict__ dst1, const int* __restrict__ dst2,
                                    float* __restrict__ ebuf, const unsigned* __restrict__ m,
                                    float* __restrict__ ssum, int E, int n) {
    int i = blockIdx.x * blockDim.x + threadIdx.x;
    if (i >= 2 * E) return;
    int set = i >= E;
    int j = i - set * E;
    int d = set ? dst2[j] : dst1[j];
    float ex = __expf(ebuf[i] - mono2f(m[set * n + d]));  // MUFU path; arg <= 0
    ebuf[i] = ex;
    atomicAdd(&ssum[set * n + d], ex);
}

// vector red: agg[d, c..c+3] += v  (16B-aligned, PTX ISA 8.1+ / sm_90+)
__device__ __forceinline__ void red_add_v4(float* p, float4 v) {
    asm volatile("red.global.add.v4.f32 [%0], {%1, %2, %3, %4};"
                 :: "l"(p), "f"(v.x), "f"(v.y), "f"(v.z), "f"(v.w)
                 : "memory");
}

// warp per edge over both sets: agg[dst] += (ex/(s+eps)) * Hs[src]
__global__ void edge_scatter2_kernel(const int* __restrict__ src1, const int* __restrict__ dst1,
                                     const int* __restrict__ src2, const int* __restrict__ dst2,
                                     const float* __restrict__ ex, const float* __restrict__ ssum,
                                     const float* __restrict__ Hs, float* __restrict__ agg,
                                     int E, int n, int C) {
    int warp = (blockIdx.x * blockDim.x + threadIdx.x) >> 5;
    int lane = threadIdx.x & 31;
    if (warp >= 2 * E) return;
    int set = warp >= E;
    int j = warp - set * E;
    int s = set ? src2[j] : src1[j];
    int d = set ? dst2[j] : dst1[j];
    float w = ex[warp] / (ssum[set * n + d] + 1e-16f);
    const float* hr = Hs + (size_t)s * C;
    float* ar = agg + (size_t)d * C;
    for (int c = lane * 4; c < C; c += 128) {
        float4 v = *(const float4*)&hr[c];
        v.x *= w; v.y *= w; v.z *= w; v.w *= w;
        red_add_v4(&ar[c], v);
    }
}

// ---------------------------------------------------------------------------
static inline void run_edge_layer(const int* src1, const int* dst1,
                                  const int* src2, const int* dst2,
                                  float* as, float* ad, unsigned* m, float* ssum,
                                  float* ebuf, const float* Hs, float* agg,
                                  int n, int E, int C) {
    int tb = 256;
    init_nodes_kernel<<<(2 * n + tb - 1) / tb, tb>>>(m, ssum, 2 * n);
    edge_max2_kernel<<<(2 * E + tb - 1) / tb, tb>>>(src1, dst1, src2, dst2, as, ad, ebuf, m, E, n);
    edge_expsum2_kernel<<<(2 * E + tb - 1) / tb, tb>>>(dst1, dst2, ebuf, m, ssum, E, n);
    edge_scatter2_kernel<<<((size_t)2 * E * 32 + tb - 1) / tb, tb>>>(src1, dst1, src2, dst2,
                                                                     ebuf, ssum, Hs, agg, E, n, C);
}

static inline void sgemm(const float* A, const float* B, const float* bias, float* C,
                         int M, int N, int K, bool relu, bool has_bias) {
    dim3 grid(N / 128, (M + 127) / 128);
    if (has_bias && relu)
        tf32_gemm_kernel<true, true><<<grid, 256>>>(A, B, bias, C, M, N, K);
    else if (has_bias)
        tf32_gemm_kernel<true, false><<<grid, 256>>>(A, B, bias, C, M, N, K);
    else
        tf32_gemm_kernel<false, false><<<grid, 256>>>(A, B, nullptr, C, M, N, K);
}

extern "C" void kernel_launch(void* const* d_in, const int* in_sizes, int n_in,
                              void* d_out, int out_size) {
    const int D = 512, H = 512, O = 256;
    const float* x   = (const float*)d_in[0];
    const int*   ei1 = (const int*)d_in[1];
    const int*   ei2 = (const int*)d_in[2];
    const float* W1s = (const float*)d_in[3];
    const float* W1d = (const float*)d_in[4];
    const float* a1s = (const float*)d_in[5];
    const float* a1d = (const float*)d_in[6];
    const float* b1  = (const float*)d_in[7];
    const float* Wl1 = (const float*)d_in[8];
    const float* bl1 = (const float*)d_in[9];
    const float* W2s = (const float*)d_in[10];
    const float* W2d = (const float*)d_in[11];
    const float* a2s = (const float*)d_in[12];
    const float* a2d = (const float*)d_in[13];
    const float* b2  = (const float*)d_in[14];
    const float* Wl2 = (const float*)d_in[15];
    const float* bl2 = (const float*)d_in[16];

    int n = in_sizes[0] / D;       // 50000
    int E = in_sizes[1] / 2;       // 150000

    void *pA, *pB, *pC, *pas, *pad, *pm, *ps, *pe, *pws, *pwd;
    cudaGetSymbolAddress(&pA, g_bufA);
    cudaGetSymbolAddress(&pB, g_bufB);
    cudaGetSymbolAddress(&pC, g_bufC);
    cudaGetSymbolAddress(&pas, g_as);
    cudaGetSymbolAddress(&pad, g_ad);
    cudaGetSymbolAddress(&pm, g_m);
    cudaGetSymbolAddress(&ps, g_ssum);
    cudaGetSymbolAddress(&pe, g_e);
    cudaGetSymbolAddress(&pws, g_ws);
    cudaGetSymbolAddress(&pwd, g_wd);
    float* bufA = (float*)pA;
    float* bufB = (float*)pB;
    float* bufC = (float*)pC;
    float* v_as = (float*)pas;
    float* v_ad = (float*)pad;
    unsigned* v_m = (unsigned*)pm;
    float* v_s = (float*)ps;
    float* ebuf = (float*)pe;
    float* v_ws = (float*)pws;
    float* v_wd = (float*)pwd;

    const int* src1 = ei1;          const int* dst1 = ei1 + E;
    const int* src2 = ei2;          const int* dst2 = ei2 + E;

    int tb = 256;

    // ---- Layer 1 ----
    matvec_kernel<<<(D * 32 + tb - 1) / tb, tb>>>(W1s, a1s, v_ws, D, H);
    matvec_kernel<<<(D * 32 + tb - 1) / tb, tb>>>(W1d, a1d, v_wd, D, H);
    dual_alpha_kernel<<<(n * 32 + tb - 1) / tb, tb>>>(x, v_ws, v_wd, v_as, v_ad, n, D);
    sgemm(x, W1s, nullptr, bufA, n, H, D, false, false);   // h1_src
    init_agg_kernel<<<(n * H + tb - 1) / tb, tb>>>(bufC, b1, 2.0f, n, H);
    run_edge_layer(src1, dst1, src2, dst2, v_as, v_ad, v_m, v_s, ebuf, bufA, bufC, n, E, H);

    // ---- lin1 + relu ----
    sgemm(bufC, Wl1, bl1, bufB, n, H, H, true, true);      // hl -> bufB

    // ---- Layer 2 ----
    matvec_kernel<<<(H * 32 + tb - 1) / tb, tb>>>(W2s, a2s, v_ws, H, O);
    matvec_kernel<<<(H * 32 + tb - 1) / tb, tb>>>(W2d, a2d, v_wd, H, O);
    dual_alpha_kernel<<<(n * 32 + tb - 1) / tb, tb>>>(bufB, v_ws, v_wd, v_as, v_ad, n, H);
    sgemm(bufB, W2s, nullptr, bufA, n, O, H, false, false); // h2_src
    init_agg_kernel<<<(n * O + tb - 1) / tb, tb>>>(bufC, b2, 2.0f, n, O);
    run_edge_layer(src1, dst1, src2, dst2, v_as, v_ad, v_m, v_s, ebuf, bufA, bufC, n, E, O);

    // ---- lin2 ----
    sgemm(bufC, Wl2, bl2, (float*)d_out, n, O, O, false, true);
}